// round 2
// baseline (speedup 1.0000x reference)
#include <cuda_runtime.h>
#include <cstdint>

#define D        256
#define KCODES   8192
#define NTOK     32768
#define BM       128
#define BK       64
#define TPB      256
#define NCHUNK   (KCODES / BK)          // 128
#define GBLOCKS  (NTOK / 8)             // 4096 gather blocks (8 tokens each)
#define ZQ_ELEMS ((size_t)NTOK * D)     // 8388608
#define OUT_FULL (ZQ_ELEMS + 3 + NTOK)  // 8421379

// ---- scratch (__device__ globals: the sanctioned no-alloc path) ----
__device__ float g_esq[KCODES];
__device__ float g_zsq[NTOK];
__device__ int   g_bidx[NTOK];
__device__ float g_part[GBLOCKS];

// ============================================================
// Kernel 0a: per-code ||e_k||^2  — sequential fma chain in d-order
// (replicates XLA-CPU scalar row-reduce with LLVM fma contraction)
// ============================================================
__global__ void esq_kernel(const float* __restrict__ emb) {
    int k = blockIdx.x * blockDim.x + threadIdx.x;
    if (k >= KCODES) return;
    const float4* row = reinterpret_cast<const float4*>(emb + (size_t)k * D);
    float s = 0.f;
#pragma unroll
    for (int i = 0; i < D / 4; ++i) {
        float4 v = row[i];
        s = fmaf(v.x, v.x, s);
        s = fmaf(v.y, v.y, s);
        s = fmaf(v.z, v.z, s);
        s = fmaf(v.w, v.w, s);
    }
    g_esq[k] = s;
}

// ============================================================
// Kernel 0b: per-token ||z_n||^2 — same sequential fma chain
// ============================================================
__global__ void zsq_kernel(const float* __restrict__ z) {
    int n = blockIdx.x * blockDim.x + threadIdx.x;
    if (n >= NTOK) return;
    const float4* row = reinterpret_cast<const float4*>(z + (size_t)n * D);
    float s = 0.f;
#pragma unroll 8
    for (int i = 0; i < D / 4; ++i) {
        float4 v = row[i];
        s = fmaf(v.x, v.x, s);
        s = fmaf(v.y, v.y, s);
        s = fmaf(v.z, v.z, s);
        s = fmaf(v.w, v.w, s);
    }
    g_zsq[n] = s;
}

// ============================================================
// Kernel 1: fused (z . e) GEMM + quantized-score argmin
//   dot_nk = sequential fmaf chain over d = 0..255 (Eigen-order)
//   score  = fl( fl(zsq + esq) - 2*dot )   <- reference's exact rounding
//   argmin = lexicographic (value, index) min — first index wins ties
// ============================================================
__global__ __launch_bounds__(TPB, 1)
void argmin_kernel(const float* __restrict__ z, const float* __restrict__ emb) {
    extern __shared__ float smem[];
    float4* zs4 = reinterpret_cast<float4*>(smem);                  // [BM][64] f4
    float4* es4 = reinterpret_cast<float4*>(smem) + (BM * D / 4);   // [BK][65] f4 (pad)

    const int tid = threadIdx.x;
    const int tx = tid & 15;
    const int ty = tid >> 4;

    // stage the 128-token z tile once
    const float4* zg4 = reinterpret_cast<const float4*>(z + (size_t)blockIdx.x * BM * D);
#pragma unroll 4
    for (int i = tid; i < BM * D / 4; i += TPB) zs4[i] = zg4[i];

    // per-thread row constants: zsq for the 8 tokens this thread owns
    float zq[8];
#pragma unroll
    for (int i = 0; i < 8; ++i) zq[i] = g_zsq[blockIdx.x * BM + ty * 8 + i];

    float best[8];
    int   bidx[8];
#pragma unroll
    for (int i = 0; i < 8; ++i) { best[i] = 3.4e38f; bidx[i] = 0; }

    for (int kc = 0; kc < NCHUNK; ++kc) {
        __syncthreads();
        const float4* eg4 = reinterpret_cast<const float4*>(emb + (size_t)kc * BK * D);
#pragma unroll 4
        for (int i = tid; i < BK * D / 4; i += TPB) {
            int row = i >> 6, c = i & 63;
            es4[row * 65 + c] = eg4[i];
        }
        __syncthreads();

        float acc[8][4];
#pragma unroll
        for (int i = 0; i < 8; ++i)
#pragma unroll
            for (int j = 0; j < 4; ++j) acc[i][j] = 0.f;

        // strictly sequential-d fma chain per accumulator (bit-matches Eigen gebp)
#pragma unroll 4
        for (int d4 = 0; d4 < D / 4; ++d4) {
            float4 zf[8];
#pragma unroll
            for (int i = 0; i < 8; ++i) zf[i] = zs4[(ty * 8 + i) * (D / 4) + d4];
            float4 ef[4];
#pragma unroll
            for (int j = 0; j < 4; ++j) ef[j] = es4[(tx + 16 * j) * 65 + d4];
#pragma unroll
            for (int i = 0; i < 8; ++i)
#pragma unroll
                for (int j = 0; j < 4; ++j) {
                    acc[i][j] = fmaf(zf[i].x, ef[j].x, acc[i][j]);
                    acc[i][j] = fmaf(zf[i].y, ef[j].y, acc[i][j]);
                    acc[i][j] = fmaf(zf[i].z, ef[j].z, acc[i][j]);
                    acc[i][j] = fmaf(zf[i].w, ef[j].w, acc[i][j]);
                }
        }

        // reference-exact score: t1 = fl(zsq + esq); s = fl(t1 - 2*dot)
#pragma unroll
        for (int j = 0; j < 4; ++j) {
            int code = kc * BK + tx + 16 * j;
            float e2 = g_esq[code];
#pragma unroll
            for (int i = 0; i < 8; ++i) {
                float t1 = __fadd_rn(zq[i], e2);
                float s  = __fadd_rn(t1, -2.0f * acc[i][j]);   // 2*acc exact
                if (s < best[i]) { best[i] = s; bidx[i] = code; }
            }
        }
    }

    // reduce across the 16 tx-threads sharing each token (lexicographic min)
#pragma unroll
    for (int m = 8; m >= 1; m >>= 1) {
#pragma unroll
        for (int i = 0; i < 8; ++i) {
            float ov = __shfl_xor_sync(0xffffffffu, best[i], m);
            int   oi = __shfl_xor_sync(0xffffffffu, bidx[i], m);
            if (ov < best[i] || (ov == best[i] && oi < bidx[i])) { best[i] = ov; bidx[i] = oi; }
        }
    }
    if (tx == 0) {
#pragma unroll
        for (int i = 0; i < 8; ++i)
            g_bidx[blockIdx.x * BM + ty * 8 + i] = bidx[i];
    }
}

// ============================================================
// Kernel 2: gather + straight-through output + loss partials
//   exact replication of fl(z + fl(e - z))
// ============================================================
__global__ void gather_kernel(const float* __restrict__ z, const float* __restrict__ emb,
                              float* __restrict__ out, int out_size) {
    __shared__ float wsum[8];
    const int lane = threadIdx.x & 31;
    const int wib  = threadIdx.x >> 5;
    const int n    = blockIdx.x * 8 + wib;   // token

    const int idx = g_bidx[n];
    const float4* zr = reinterpret_cast<const float4*>(z   + (size_t)n   * D);
    const float4* er = reinterpret_cast<const float4*>(emb + (size_t)idx * D);
    float4* orow = reinterpret_cast<float4*>(out + (size_t)n * D);

    float ss = 0.f;
#pragma unroll
    for (int i = lane; i < D / 4; i += 32) {
        float4 zv = zr[i], ev = er[i], df, ov;
        df.x = ev.x - zv.x; df.y = ev.y - zv.y; df.z = ev.z - zv.z; df.w = ev.w - zv.w;
        ov.x = zv.x + df.x; ov.y = zv.y + df.y; ov.z = zv.z + df.z; ov.w = zv.w + df.w;
        ss = fmaf(df.x, df.x, ss); ss = fmaf(df.y, df.y, ss);
        ss = fmaf(df.z, df.z, ss); ss = fmaf(df.w, df.w, ss);
        if ((size_t)out_size >= ZQ_ELEMS) orow[i] = ov;
    }
#pragma unroll
    for (int m = 16; m >= 1; m >>= 1) ss += __shfl_xor_sync(0xffffffffu, ss, m);
    if (lane == 0) wsum[wib] = ss;
    __syncthreads();
    if (threadIdx.x == 0) {
        float t = 0.f;
#pragma unroll
        for (int w = 0; w < 8; ++w) t += wsum[w];   // fixed order, deterministic
        g_part[blockIdx.x] = t;
    }
    if (lane == 0 && (size_t)out_size >= OUT_FULL)
        out[ZQ_ELEMS + 3 + n] = (float)idx;
}

// ============================================================
// Kernel 3: deterministic loss finalize (double accumulation)
// ============================================================
__global__ void loss_kernel(float* __restrict__ out, int out_size) {
    __shared__ double sh[256];
    const int t = threadIdx.x;
    double s = 0.0;
#pragma unroll 4
    for (int i = t * (GBLOCKS / 256); i < (t + 1) * (GBLOCKS / 256); ++i)
        s += (double)g_part[i];
    sh[t] = s;
    __syncthreads();
    for (int m = 128; m >= 1; m >>= 1) {
        if (t < m) sh[t] += sh[t + m];
        __syncthreads();
    }
    if (t == 0 && (size_t)out_size >= ZQ_ELEMS + 3) {
        float mean = (float)(sh[0] / (double)ZQ_ELEMS);
        float commit   = 0.25f * mean;
        float codebook = mean;
        out[ZQ_ELEMS + 0] = commit + codebook;
        out[ZQ_ELEMS + 1] = commit;
        out[ZQ_ELEMS + 2] = codebook;
    }
}

// ============================================================
extern "C" void kernel_launch(void* const* d_in, const int* in_sizes, int n_in,
                              void* d_out, int out_size) {
    const float* z   = (const float*)d_in[0];
    const float* emb = (const float*)d_in[1];
    if (n_in >= 2 && in_sizes[0] == KCODES * D && in_sizes[1] == NTOK * D) {
        z   = (const float*)d_in[1];
        emb = (const float*)d_in[0];
    }
    float* out = (float*)d_out;

    static bool attr_set = false;
    const int smem_bytes = (BM * D + BK * 260) * (int)sizeof(float);   // 197632
    if (!attr_set) {
        cudaFuncSetAttribute(argmin_kernel,
                             cudaFuncAttributeMaxDynamicSharedMemorySize, smem_bytes);
        attr_set = true;
    }

    esq_kernel<<<KCODES / 128, 128>>>(emb);
    zsq_kernel<<<NTOK / 256, 256>>>(z);
    argmin_kernel<<<NTOK / BM, TPB, smem_bytes>>>(z, emb);
    gather_kernel<<<GBLOCKS, 256>>>(z, emb, out, out_size);
    loss_kernel<<<1, 256>>>(out, out_size);
}